// round 5
// baseline (speedup 1.0000x reference)
#include <cuda_runtime.h>
#include <math.h>

typedef unsigned long long ull;

#define BB 64
#define TT 512
#define II 256
#define HH 512
#define CC 40
#define G4 2048     // 4*H
#define NB 128      // persistent blocks, all co-resident (<=148 SMs, 1 block/SM)

// -------------------- device scratch --------------------
__device__ __align__(256) float g_xg [(size_t)BB * TT * G4];   // [m=b*T+t][n]
__device__ __align__(256) float g_xgT[(size_t)TT * G4 * BB];   // [t][n][b]
__device__ __align__(256) float g_hbuf[2 * HH * BB];           // [parity][unit][b]
__device__ volatile unsigned g_flags[NB * 32];                 // one 128B line per block
__device__ volatile unsigned g_gen2;                           // generation word

// -------------------- f32x2 helpers --------------------
__device__ __forceinline__ ull pack2(float x, float y) {
    ull r; asm("mov.b64 %0, {%1, %2};" : "=l"(r) : "f"(x), "f"(y)); return r;
}
__device__ __forceinline__ void unpack2(ull v, float& x, float& y) {
    asm("mov.b64 {%0, %1}, %2;" : "=f"(x), "=f"(y) : "l"(v));
}
__device__ __forceinline__ ull ffma2(ull a, ull b, ull c) {
    ull d; asm("fma.rn.f32x2 %0, %1, %2, %3;" : "=l"(d) : "l"(a), "l"(b), "l"(c)); return d;
}

// fast activations (MUFU-based; err ~1e-6, well within 1e-3 budget)
__device__ __forceinline__ float fsig(float x) {
    return __fdividef(1.f, 1.f + __expf(-x));
}
__device__ __forceinline__ float ftanh(float x) {
    float ax = fabsf(x);
    float e  = __expf(-2.f * ax);
    float r  = __fdividef(1.f - e, 1.f + e);
    return x < 0.f ? -r : r;
}

// -------------------- flag-tree grid barrier --------------------
__device__ __forceinline__ void gridbar(int bx, int tid, unsigned e) {
    __threadfence();
    __syncthreads();
    if (bx == 0) {
        if (tid > 0 && tid < NB) {
            while ((int)(g_flags[tid * 32] - e) < 0) { }
        }
        __syncthreads();
        if (tid == 0) { __threadfence(); g_gen2 = e; }
    } else {
        if (tid == 0) {
            g_flags[bx * 32] = e;
            while ((int)(g_gen2 - e) < 0) { __nanosleep(16); }
            __threadfence();
        }
        __syncthreads();
    }
}

// -------------------- kernel 1: xg = x @ W_ih^T + (b_ih + b_hh), f32x2 --------------------
// Bs uses a chunk-permuted layout: chunk m (cols 4m..4m+3) of row k lives at byte
// k*528 + (m&3)*128 + (m>>2)*16.  Turns the 4-way-conflicted b-loads into uniform 2-way.
__global__ void __launch_bounds__(256) gemm_xg(const float* __restrict__ x,
                                               const float* __restrict__ Wih,
                                               const float* __restrict__ bih,
                                               const float* __restrict__ bhh) {
    __shared__ __align__(16) float As[16][132];   // [k][m]
    __shared__ __align__(16) float Bs[16][132];   // [k][n] permuted
    const int tid  = threadIdx.x;
    const int m0   = blockIdx.y * 128;
    const int n0   = blockIdx.x * 128;
    const int tx   = tid & 15;
    const int ty   = tid >> 4;
    const int lrow = tid >> 2;
    const int lkq  = (tid & 3) << 2;
    char* BsB = (char*)Bs;

    ull acc2[8][4];
#pragma unroll
    for (int i = 0; i < 8; i++)
#pragma unroll
        for (int j = 0; j < 4; j++) acc2[i][j] = 0ull;

    const unsigned posA = ((unsigned)(tx & 1)) * 256u + ((unsigned)(tx >> 1)) * 16u;

    for (int k0 = 0; k0 < II; k0 += 16) {
        float4 a0 = *(const float4*)(x   + (size_t)(m0 + lrow)      * II + k0 + lkq);
        float4 a1 = *(const float4*)(x   + (size_t)(m0 + lrow + 64) * II + k0 + lkq);
        float4 b0 = *(const float4*)(Wih + (size_t)(n0 + lrow)      * II + k0 + lkq);
        float4 b1 = *(const float4*)(Wih + (size_t)(n0 + lrow + 64) * II + k0 + lkq);
        __syncthreads();
        As[lkq+0][lrow]    = a0.x; As[lkq+1][lrow]    = a0.y;
        As[lkq+2][lrow]    = a0.z; As[lkq+3][lrow]    = a0.w;
        As[lkq+0][lrow+64] = a1.x; As[lkq+1][lrow+64] = a1.y;
        As[lkq+2][lrow+64] = a1.z; As[lkq+3][lrow+64] = a1.w;
        {
            // permuted scalar stores: col c -> off(kk,c)
            int c0 = lrow, c1 = lrow + 64;
            unsigned o0 = (unsigned)(((c0 >> 2) & 3) << 7) + (unsigned)((c0 >> 4) << 4) + (unsigned)((c0 & 3) << 2);
            unsigned o1 = (unsigned)(((c1 >> 2) & 3) << 7) + (unsigned)((c1 >> 4) << 4) + (unsigned)((c1 & 3) << 2);
            *(float*)(BsB + (lkq+0)*528 + o0) = b0.x;
            *(float*)(BsB + (lkq+1)*528 + o0) = b0.y;
            *(float*)(BsB + (lkq+2)*528 + o0) = b0.z;
            *(float*)(BsB + (lkq+3)*528 + o0) = b0.w;
            *(float*)(BsB + (lkq+0)*528 + o1) = b1.x;
            *(float*)(BsB + (lkq+1)*528 + o1) = b1.y;
            *(float*)(BsB + (lkq+2)*528 + o1) = b1.z;
            *(float*)(BsB + (lkq+3)*528 + o1) = b1.w;
        }
        __syncthreads();
#pragma unroll
        for (int k = 0; k < 16; k++) {
            float a[8];
            *(float4*)(a)     = *(float4*)&As[k][ty * 8];
            *(float4*)(a + 4) = *(float4*)&As[k][ty * 8 + 4];
            ulonglong2 bA = *(ulonglong2*)(BsB + k*528 + posA);
            ulonglong2 bB = *(ulonglong2*)(BsB + k*528 + posA + 128);
            ull b2[4] = {bA.x, bA.y, bB.x, bB.y};
#pragma unroll
            for (int i = 0; i < 8; i++) {
                ull a2 = pack2(a[i], a[i]);
                acc2[i][0] = ffma2(a2, b2[0], acc2[i][0]);
                acc2[i][1] = ffma2(a2, b2[1], acc2[i][1]);
                acc2[i][2] = ffma2(a2, b2[2], acc2[i][2]);
                acc2[i][3] = ffma2(a2, b2[3], acc2[i][3]);
            }
        }
    }

    float bias[8];
#pragma unroll
    for (int j = 0; j < 8; j++) {
        int n = n0 + tx * 8 + j;
        bias[j] = bih[n] + bhh[n];
    }
#pragma unroll
    for (int i = 0; i < 8; i++) {
        size_t m = (size_t)(m0 + ty * 8 + i);
        float o[8];
#pragma unroll
        for (int j = 0; j < 4; j++) unpack2(acc2[i][j], o[2*j], o[2*j+1]);
        float4 v0, v1;
        v0.x = o[0] + bias[0]; v0.y = o[1] + bias[1];
        v0.z = o[2] + bias[2]; v0.w = o[3] + bias[3];
        v1.x = o[4] + bias[4]; v1.y = o[5] + bias[5];
        v1.z = o[6] + bias[6]; v1.w = o[7] + bias[7];
        *(float4*)(g_xg + m * G4 + n0 + tx * 8)     = v0;
        *(float4*)(g_xg + m * G4 + n0 + tx * 8 + 4) = v1;
    }
}

// -------------------- kernel 2: transpose xg[b*T+t][n] -> xgT[t][n][b] --------------------
__global__ void __launch_bounds__(256) transpose_xg() {
    __shared__ float tile[64][65];
    const int t   = blockIdx.x;
    const int n0  = blockIdx.y << 6;
    const int tid = threadIdx.x;
    const int a   = tid & 63;
    const int r   = tid >> 6;
    for (int b = r; b < 64; b += 4)
        tile[a][b] = g_xg[(size_t)(b * TT + t) * G4 + n0 + a];
    __syncthreads();
    for (int n = r; n < 64; n += 4)
        g_xgT[((size_t)t * G4 + n0 + n) * BB + a] = tile[n][a];
}

// -------------------- kernel 3: persistent LSTM recurrence --------------------
// Conflict-free design:
//   warp = one k-split (8 warps x krange 64), lane = (rq 0..3, bq 0..7),
//   thread tile = 4 rows x 8 batches.
//   hsT: [k][chunk-permuted 64 floats], chunk m at (m&1)*128 + (m>>1)*16
//        -> h LDS.128: 8 distinct chunks at {0,16,..,112} mod 128 = 1 phase, rq-broadcast.
//   Wsm: [k][16 dup-ulls] (128B rows) -> w LDS.128 at rq*32: distinct banks, bq-broadcast.
// smem: hsT 128KB | Wsm 64KB | red 8x16x64 floats 32KB  = 224KB
#define SMEM_LSTM (131072 + 65536 + 32768)
__global__ void __launch_bounds__(256, 1) lstm_rec(const float* __restrict__ Whh) {
    extern __shared__ char smc[];
    ull*   hsT2 = (ull*)smc;                     // [512][32] permuted h
    ull*   Wsm2 = (ull*)(smc + 131072);          // [512][16] {w,w}
    float* red  = (float*)(smc + 131072 + 65536);// [8][16][64]
    ull*   red2 = (ull*)red;

    const int tid = threadIdx.x;
    const int bx  = blockIdx.x;
    unsigned base = g_gen2;   // persistent epoch base

    // Load W_hh slice: Wsm2[k*16 + lr] = dup(Whh[row(lr)][k]), lr = g*4+uu
    for (int idx = tid; idx < 16 * 512; idx += 256) {
        int k   = idx >> 4;
        int lr  = idx & 15;
        int row = ((lr >> 2) << 9) + (bx << 2) + (lr & 3);
        float w = Whh[(size_t)row * HH + k];
        Wsm2[(k << 4) + lr] = pack2(w, w);
    }

    // elementwise-role mapping
    const int b  = tid & 63;
    const int uu = tid >> 6;
    const int ug = (bx << 2) + uu;

    g_hbuf[ug * 64 + b] = 0.f;    // h0 = 0 (parity 0)
    float c = 0.f;
    unsigned e = base + 1;
    gridbar(bx, tid, e); e++;

    // compute-role mapping
    const int kg   = tid >> 5;      // warp id = k-split, krange 64
    const int lane = tid & 31;
    const int rq   = lane >> 3;     // rows 4rq..4rq+3
    const int bq   = lane & 7;      // batches 8bq..8bq+7
    const int kbeg = kg << 6;

    // stage-address permutation (per-thread constant)
    unsigned sdst0;
    { int m0 = tid & 15; int kk = tid >> 4;
      sdst0 = (unsigned)(kk * 256 + ((m0 & 1) << 7) + ((m0 >> 1) << 4)); }
    const unsigned sbase = (unsigned)__cvta_generic_to_shared(smc);
    const int rb = (kg << 9) + ((rq << 2)) * 32 + (bq << 2);  // red2 ull base (row j adds j*32)

    for (int t = 0; t < TT; t++) {
        const int p = t & 1;

        // prefetch xg for this step (independent of h)
        float xgv[4];
#pragma unroll
        for (int g = 0; g < 4; g++)
            xgv[g] = __ldg(&g_xgT[((size_t)t * G4 + (g << 9) + ug) * 64 + b]);

        // stage h (chunk-permuted) via cp.async.cg
        {
            const char* g0 = (const char*)(g_hbuf + p * HH * 64) + tid * 16;
#pragma unroll
            for (int i = 0; i < 32; i++)
                asm volatile("cp.async.cg.shared.global [%0], [%1], 16;"
                             :: "r"(sbase + sdst0 + i * 4096), "l"(g0 + i * 4096));
            asm volatile("cp.async.commit_group;");
            asm volatile("cp.async.wait_group 0;");
        }
        __syncthreads();

        ull acc[4][4];
#pragma unroll
        for (int j = 0; j < 4; j++)
#pragma unroll
            for (int u = 0; u < 4; u++) acc[j][u] = 0ull;

        const ull* hk = hsT2 + (kbeg << 5) + (bq << 1);
        const ull* wk = Wsm2 + (kbeg << 4) + (rq << 2);
#pragma unroll 8
        for (int k = 0; k < 64; k++) {
            ulonglong2 ha = *(const ulonglong2*)(hk);        // batches 8bq..+3
            ulonglong2 hb = *(const ulonglong2*)(hk + 16);   // batches 8bq+4..+7
            ulonglong2 wa = *(const ulonglong2*)(wk);        // rows 4rq, 4rq+1 (dup)
            ulonglong2 wb = *(const ulonglong2*)(wk + 2);    // rows 4rq+2, 4rq+3 (dup)
            hk += 32; wk += 16;
            acc[0][0] = ffma2(wa.x, ha.x, acc[0][0]);
            acc[0][1] = ffma2(wa.x, ha.y, acc[0][1]);
            acc[0][2] = ffma2(wa.x, hb.x, acc[0][2]);
            acc[0][3] = ffma2(wa.x, hb.y, acc[0][3]);
            acc[1][0] = ffma2(wa.y, ha.x, acc[1][0]);
            acc[1][1] = ffma2(wa.y, ha.y, acc[1][1]);
            acc[1][2] = ffma2(wa.y, hb.x, acc[1][2]);
            acc[1][3] = ffma2(wa.y, hb.y, acc[1][3]);
            acc[2][0] = ffma2(wb.x, ha.x, acc[2][0]);
            acc[2][1] = ffma2(wb.x, ha.y, acc[2][1]);
            acc[2][2] = ffma2(wb.x, hb.x, acc[2][2]);
            acc[2][3] = ffma2(wb.x, hb.y, acc[2][3]);
            acc[3][0] = ffma2(wb.y, ha.x, acc[3][0]);
            acc[3][1] = ffma2(wb.y, ha.y, acc[3][1]);
            acc[3][2] = ffma2(wb.y, hb.x, acc[3][2]);
            acc[3][3] = ffma2(wb.y, hb.y, acc[3][3]);
        }

#pragma unroll
        for (int j = 0; j < 4; j++) {
            *(ulonglong2*)(red2 + rb + j * 32)     = make_ulonglong2(acc[j][0], acc[j][1]);
            *(ulonglong2*)(red2 + rb + j * 32 + 2) = make_ulonglong2(acc[j][2], acc[j][3]);
        }
        __syncthreads();

        // elementwise: combine 8 split-k partials + xg, gates, state update
        float s[4];
#pragma unroll
        for (int g = 0; g < 4; g++) {
            int lr = (g << 2) + uu;
            float v = 0.f;
#pragma unroll
            for (int k2 = 0; k2 < 8; k2++)
                v += red[(k2 << 10) + lr * 64 + b];
            s[g] = v + xgv[g];
        }
        float ig = fsig(s[0]);
        float fg = fsig(s[1]);
        float gg = ftanh(s[2]);
        float og = fsig(s[3]);
        c = fmaf(fg, c, ig * gg);
        float h = og * ftanh(c);
        g_hbuf[((p ^ 1) * HH + ug) * 64 + b] = h;
        gridbar(bx, tid, e); e++;
    }
    // h_last in parity 0
}

// -------------------- kernel 4: out = h_last @ W_fc^T + b_fc --------------------
__global__ void __launch_bounds__(256) fc_out(const float* __restrict__ Wfc,
                                              const float* __restrict__ bfc,
                                              float* __restrict__ out) {
    __shared__ float hs[HH];
    const int b = blockIdx.x;
    for (int u = threadIdx.x; u < HH; u += 256) hs[u] = g_hbuf[u * 64 + b];
    __syncthreads();
    const int w = threadIdx.x >> 5, lane = threadIdx.x & 31;
    for (int cc = w; cc < CC; cc += 8) {
        float s = 0.f;
        for (int u = lane; u < HH; u += 32) s = fmaf(hs[u], Wfc[cc * HH + u], s);
#pragma unroll
        for (int o = 16; o; o >>= 1) s += __shfl_xor_sync(0xffffffffu, s, o);
        if (lane == 0) out[b * CC + cc] = s + bfc[cc];
    }
}

// -------------------- launch --------------------
extern "C" void kernel_launch(void* const* d_in, const int* in_sizes, int n_in,
                              void* d_out, int out_size) {
    (void)in_sizes; (void)n_in; (void)out_size;
    const float* x   = (const float*)d_in[0];
    const float* Wih = (const float*)d_in[1];
    const float* Whh = (const float*)d_in[2];
    const float* bih = (const float*)d_in[3];
    const float* bhh = (const float*)d_in[4];
    const float* Wfc = (const float*)d_in[5];
    const float* bfc = (const float*)d_in[6];
    float* out = (float*)d_out;

    gemm_xg<<<dim3(G4 / 128, (BB * TT) / 128), 256>>>(x, Wih, bih, bhh);
    transpose_xg<<<dim3(TT, G4 / 64), 256>>>();

    cudaFuncSetAttribute(lstm_rec, cudaFuncAttributeMaxDynamicSharedMemorySize, SMEM_LSTM);
    lstm_rec<<<NB, 256, SMEM_LSTM>>>(Whh);

    fc_out<<<BB, 256>>>(Wfc, bfc, out);
}

// round 6
// speedup vs baseline: 1.6903x; 1.6903x over previous
#include <cuda_runtime.h>
#include <math.h>

typedef unsigned long long ull;

#define BB 64
#define TT 512
#define II 256
#define HH 512
#define CC 40
#define G4 2048     // 4*H
#define NB 128      // persistent blocks, all co-resident (<=148 SMs, 1 block/SM)

// -------------------- device scratch --------------------
__device__ __align__(256) float g_xg [(size_t)BB * TT * G4];   // [m=b*T+t][n]
__device__ __align__(256) float g_xgT[(size_t)TT * G4 * BB];   // [t][n][b]
__device__ __align__(256) float g_hbuf[2 * HH * BB];           // [parity][unit][b]
__device__ volatile unsigned g_stepflag[NB * 32];              // one 128B line per block

// -------------------- f32x2 helpers --------------------
__device__ __forceinline__ ull pack2(float x, float y) {
    ull r; asm("mov.b64 %0, {%1, %2};" : "=l"(r) : "f"(x), "f"(y)); return r;
}
__device__ __forceinline__ void unpack2(ull v, float& x, float& y) {
    asm("mov.b64 {%0, %1}, %2;" : "=f"(x), "=f"(y) : "l"(v));
}
__device__ __forceinline__ ull ffma2(ull a, ull b, ull c) {
    ull d; asm("fma.rn.f32x2 %0, %1, %2, %3;" : "=l"(d) : "l"(a), "l"(b), "l"(c)); return d;
}
// 32B L2 (.cg) load as two ulls
__device__ __forceinline__ void ldcg32(const void* p, ull& a, ull& b, ull& c, ull& d) {
    asm volatile("ld.global.cg.v2.u64 {%0, %1}, [%2];" : "=l"(a), "=l"(b) : "l"(p));
    asm volatile("ld.global.cg.v2.u64 {%0, %1}, [%2];" : "=l"(c), "=l"(d) : "l"((const char*)p + 16));
}

// fast activations (MUFU-based; err ~1e-6, well within 1e-3 budget)
__device__ __forceinline__ float fsig(float x) {
    return __fdividef(1.f, 1.f + __expf(-x));
}
__device__ __forceinline__ float ftanh(float x) {
    float ax = fabsf(x);
    float e  = __expf(-2.f * ax);
    float r  = __fdividef(1.f - e, 1.f + e);
    return x < 0.f ? -r : r;
}

// -------------------- kernel 1: xg = x @ W_ih^T + (b_ih + b_hh), f32x2 --------------------
__global__ void __launch_bounds__(256) gemm_xg(const float* __restrict__ x,
                                               const float* __restrict__ Wih,
                                               const float* __restrict__ bih,
                                               const float* __restrict__ bhh) {
    __shared__ __align__(16) float As[16][132];   // [k][m]
    __shared__ __align__(16) float Bs[16][132];   // [k][n] permuted
    const int tid  = threadIdx.x;
    const int m0   = blockIdx.y * 128;
    const int n0   = blockIdx.x * 128;
    const int tx   = tid & 15;
    const int ty   = tid >> 4;
    const int lrow = tid >> 2;
    const int lkq  = (tid & 3) << 2;
    char* BsB = (char*)Bs;

    ull acc2[8][4];
#pragma unroll
    for (int i = 0; i < 8; i++)
#pragma unroll
        for (int j = 0; j < 4; j++) acc2[i][j] = 0ull;

    const unsigned posA = ((unsigned)(tx & 1)) * 256u + ((unsigned)(tx >> 1)) * 16u;

    for (int k0 = 0; k0 < II; k0 += 16) {
        float4 a0 = *(const float4*)(x   + (size_t)(m0 + lrow)      * II + k0 + lkq);
        float4 a1 = *(const float4*)(x   + (size_t)(m0 + lrow + 64) * II + k0 + lkq);
        float4 b0 = *(const float4*)(Wih + (size_t)(n0 + lrow)      * II + k0 + lkq);
        float4 b1 = *(const float4*)(Wih + (size_t)(n0 + lrow + 64) * II + k0 + lkq);
        __syncthreads();
        As[lkq+0][lrow]    = a0.x; As[lkq+1][lrow]    = a0.y;
        As[lkq+2][lrow]    = a0.z; As[lkq+3][lrow]    = a0.w;
        As[lkq+0][lrow+64] = a1.x; As[lkq+1][lrow+64] = a1.y;
        As[lkq+2][lrow+64] = a1.z; As[lkq+3][lrow+64] = a1.w;
        {
            int c0 = lrow, c1 = lrow + 64;
            unsigned o0 = (unsigned)(((c0 >> 2) & 3) << 7) + (unsigned)((c0 >> 4) << 4) + (unsigned)((c0 & 3) << 2);
            unsigned o1 = (unsigned)(((c1 >> 2) & 3) << 7) + (unsigned)((c1 >> 4) << 4) + (unsigned)((c1 & 3) << 2);
            *(float*)(BsB + (lkq+0)*528 + o0) = b0.x;
            *(float*)(BsB + (lkq+1)*528 + o0) = b0.y;
            *(float*)(BsB + (lkq+2)*528 + o0) = b0.z;
            *(float*)(BsB + (lkq+3)*528 + o0) = b0.w;
            *(float*)(BsB + (lkq+0)*528 + o1) = b1.x;
            *(float*)(BsB + (lkq+1)*528 + o1) = b1.y;
            *(float*)(BsB + (lkq+2)*528 + o1) = b1.z;
            *(float*)(BsB + (lkq+3)*528 + o1) = b1.w;
        }
        __syncthreads();
#pragma unroll
        for (int k = 0; k < 16; k++) {
            float a[8];
            *(float4*)(a)     = *(float4*)&As[k][ty * 8];
            *(float4*)(a + 4) = *(float4*)&As[k][ty * 8 + 4];
            ulonglong2 bA = *(ulonglong2*)(BsB + k*528 + posA);
            ulonglong2 bB = *(ulonglong2*)(BsB + k*528 + posA + 128);
            ull b2[4] = {bA.x, bA.y, bB.x, bB.y};
#pragma unroll
            for (int i = 0; i < 8; i++) {
                ull a2 = pack2(a[i], a[i]);
                acc2[i][0] = ffma2(a2, b2[0], acc2[i][0]);
                acc2[i][1] = ffma2(a2, b2[1], acc2[i][1]);
                acc2[i][2] = ffma2(a2, b2[2], acc2[i][2]);
                acc2[i][3] = ffma2(a2, b2[3], acc2[i][3]);
            }
        }
    }

    float bias[8];
#pragma unroll
    for (int j = 0; j < 8; j++) {
        int n = n0 + tx * 8 + j;
        bias[j] = bih[n] + bhh[n];
    }
#pragma unroll
    for (int i = 0; i < 8; i++) {
        size_t m = (size_t)(m0 + ty * 8 + i);
        float o[8];
#pragma unroll
        for (int j = 0; j < 4; j++) unpack2(acc2[i][j], o[2*j], o[2*j+1]);
        float4 v0, v1;
        v0.x = o[0] + bias[0]; v0.y = o[1] + bias[1];
        v0.z = o[2] + bias[2]; v0.w = o[3] + bias[3];
        v1.x = o[4] + bias[4]; v1.y = o[5] + bias[5];
        v1.z = o[6] + bias[6]; v1.w = o[7] + bias[7];
        *(float4*)(g_xg + m * G4 + n0 + tx * 8)     = v0;
        *(float4*)(g_xg + m * G4 + n0 + tx * 8 + 4) = v1;
    }
}

// -------------------- kernel 2: transpose xg[b*T+t][n] -> xgT[t][n][b] --------------------
__global__ void __launch_bounds__(256) transpose_xg() {
    __shared__ float tile[64][65];
    const int t   = blockIdx.x;
    const int n0  = blockIdx.y << 6;
    const int tid = threadIdx.x;
    const int a   = tid & 63;
    const int r   = tid >> 6;
    for (int b = r; b < 64; b += 4)
        tile[a][b] = g_xg[(size_t)(b * TT + t) * G4 + n0 + a];
    __syncthreads();
    for (int n = r; n < 64; n += 4)
        g_xgT[((size_t)t * G4 + n0 + n) * BB + a] = tile[n][a];
}

// -------------------- kernel 3: persistent LSTM recurrence --------------------
// Dataflow-synced, zero-staging design:
//  * Block bx owns units [4bx,4bx+4) -> 16 gate rows. Warp kg owns k-split
//    [64kg, 64kg+64): it polls only its 16 producer blocks' flags, then reads
//    its 16KB h slice DIRECTLY from L2 (ld.global.cg) inside the FMA loop.
//  * Producer publishes flag[bx] = S+1+t after writing h_t. One L2 round trip
//    of sync per step; producers never wait for consumers (double-buffered h,
//    flag lag >= 2 steps guarantees safe reuse).
// smem: Wsm2 [512][16] dup-pairs 64KB | red [8][16][64] 32KB   = 96KB
#define SMEM_LSTM (65536 + 32768)
__global__ void __launch_bounds__(256, 1) lstm_rec(const float* __restrict__ Whh) {
    extern __shared__ char smc[];
    ull*   Wsm2 = (ull*)smc;                 // [512][16] {w,w}
    float* red  = (float*)(smc + 65536);     // [8][16][64]
    ull*   red2 = (ull*)red;

    const int tid = threadIdx.x;
    const int bx  = blockIdx.x;
    const unsigned S = g_stepflag[bx * 32];  // own flag: consistent epoch base

    // Load W_hh slice: Wsm2[k*16 + lr] = dup(Whh[row(lr)][k]), lr = g*4+uu
    for (int idx = tid; idx < 16 * 512; idx += 256) {
        int k   = idx >> 4;
        int lr  = idx & 15;
        int row = ((lr >> 2) << 9) + (bx << 2) + (lr & 3);
        float w = Whh[(size_t)row * HH + k];
        Wsm2[(k << 4) + lr] = pack2(w, w);
    }

    // elementwise-role mapping
    const int b  = tid & 63;
    const int uu = tid >> 6;
    const int ug = (bx << 2) + uu;

    g_hbuf[ug * 64 + b] = 0.f;    // h0 = 0 (parity 0)
    float c = 0.f;
    __syncthreads();
    if (tid == 0) { __threadfence(); g_stepflag[bx * 32] = S + 1; }  // h_0 ready

    // compute-role mapping
    const int kg   = tid >> 5;      // warp id = k-split, krange 64
    const int lane = tid & 31;
    const int rq   = lane >> 3;     // rows 4rq..4rq+3
    const int bq   = lane & 7;      // batches 8bq..8bq+7
    const int prod = ((kg << 4) + (lane & 15)) * 32;   // producer flag index
    const ull* wk0 = Wsm2 + ((kg << 6) << 4) + (rq << 2);
    const int rb = (kg << 9) + (rq << 2) * 32 + (bq << 2);  // red2 ull base

    for (int t = 0; t < TT; t++) {
        const int p = t & 1;

        // prefetch xg for this step (independent of h)
        float xgv[4];
#pragma unroll
        for (int g = 0; g < 4; g++)
            xgv[g] = __ldg(&g_xgT[((size_t)t * G4 + (g << 9) + ug) * 64 + b]);

        // wait for this warp's 16 producers to have published h_t
        {
            const unsigned want = S + 1 + (unsigned)t;
            while ((int)(g_stepflag[prod] - want) < 0) { }
            __syncwarp();
            __threadfence();   // acquire: order h reads after flag observation
        }

        ull acc[4][4];
#pragma unroll
        for (int j = 0; j < 4; j++)
#pragma unroll
            for (int u = 0; u < 4; u++) acc[j][u] = 0ull;

        const char* hk = (const char*)(g_hbuf + (size_t)p * HH * 64)
                       + ((kg << 6) << 8) + (bq << 5);       // k*256B + bq*32B
        const ull* wk = wk0;
#pragma unroll 8
        for (int k = 0; k < 64; k++) {
            ull hx, hy, hz, hw;
            ldcg32(hk, hx, hy, hz, hw);                       // 8 batches of h[k]
            ulonglong2 wa = *(const ulonglong2*)(wk);         // rows 4rq,4rq+1 (dup)
            ulonglong2 wb = *(const ulonglong2*)(wk + 2);     // rows 4rq+2,4rq+3
            hk += 256; wk += 16;
            acc[0][0] = ffma2(wa.x, hx, acc[0][0]);
            acc[0][1] = ffma2(wa.x, hy, acc[0][1]);
            acc[0][2] = ffma2(wa.x, hz, acc[0][2]);
            acc[0][3] = ffma2(wa.x, hw, acc[0][3]);
            acc[1][0] = ffma2(wa.y, hx, acc[1][0]);
            acc[1][1] = ffma2(wa.y, hy, acc[1][1]);
            acc[1][2] = ffma2(wa.y, hz, acc[1][2]);
            acc[1][3] = ffma2(wa.y, hw, acc[1][3]);
            acc[2][0] = ffma2(wb.x, hx, acc[2][0]);
            acc[2][1] = ffma2(wb.x, hy, acc[2][1]);
            acc[2][2] = ffma2(wb.x, hz, acc[2][2]);
            acc[2][3] = ffma2(wb.x, hw, acc[2][3]);
            acc[3][0] = ffma2(wb.y, hx, acc[3][0]);
            acc[3][1] = ffma2(wb.y, hy, acc[3][1]);
            acc[3][2] = ffma2(wb.y, hz, acc[3][2]);
            acc[3][3] = ffma2(wb.y, hw, acc[3][3]);
        }

#pragma unroll
        for (int j = 0; j < 4; j++) {
            *(ulonglong2*)(red2 + rb + j * 32)     = make_ulonglong2(acc[j][0], acc[j][1]);
            *(ulonglong2*)(red2 + rb + j * 32 + 2) = make_ulonglong2(acc[j][2], acc[j][3]);
        }
        __syncthreads();

        // elementwise: combine 8 split-k partials + xg, gates, state update
        float s[4];
#pragma unroll
        for (int g = 0; g < 4; g++) {
            int lr = (g << 2) + uu;
            float v = 0.f;
#pragma unroll
            for (int k2 = 0; k2 < 8; k2++)
                v += red[(k2 << 10) + lr * 64 + b];
            s[g] = v + xgv[g];
        }
        float ig = fsig(s[0]);
        float fg = fsig(s[1]);
        float gg = ftanh(s[2]);
        float og = fsig(s[3]);
        c = fmaf(fg, c, ig * gg);
        float h = og * ftanh(c);
        g_hbuf[((p ^ 1) * HH + ug) * 64 + b] = h;
        __syncthreads();   // all h writes of this block done
        if (tid == 0) { __threadfence(); g_stepflag[bx * 32] = S + 2 + (unsigned)t; }
    }
    // h_last = h_512 in parity 0
}

// -------------------- kernel 4: out = h_last @ W_fc^T + b_fc --------------------
__global__ void __launch_bounds__(256) fc_out(const float* __restrict__ Wfc,
                                              const float* __restrict__ bfc,
                                              float* __restrict__ out) {
    __shared__ float hs[HH];
    const int b = blockIdx.x;
    for (int u = threadIdx.x; u < HH; u += 256) hs[u] = g_hbuf[u * 64 + b];
    __syncthreads();
    const int w = threadIdx.x >> 5, lane = threadIdx.x & 31;
    for (int cc = w; cc < CC; cc += 8) {
        float s = 0.f;
        for (int u = lane; u < HH; u += 32) s = fmaf(hs[u], Wfc[cc * HH + u], s);
#pragma unroll
        for (int o = 16; o; o >>= 1) s += __shfl_xor_sync(0xffffffffu, s, o);
        if (lane == 0) out[b * CC + cc] = s + bfc[cc];
    }
}

// -------------------- launch --------------------
extern "C" void kernel_launch(void* const* d_in, const int* in_sizes, int n_in,
                              void* d_out, int out_size) {
    (void)in_sizes; (void)n_in; (void)out_size;
    const float* x   = (const float*)d_in[0];
    const float* Wih = (const float*)d_in[1];
    const float* Whh = (const float*)d_in[2];
    const float* bih = (const float*)d_in[3];
    const float* bhh = (const float*)d_in[4];
    const float* Wfc = (const float*)d_in[5];
    const float* bfc = (const float*)d_in[6];
    float* out = (float*)d_out;

    gemm_xg<<<dim3(G4 / 128, (BB * TT) / 128), 256>>>(x, Wih, bih, bhh);
    transpose_xg<<<dim3(TT, G4 / 64), 256>>>();

    cudaFuncSetAttribute(lstm_rec, cudaFuncAttributeMaxDynamicSharedMemorySize, SMEM_LSTM);
    lstm_rec<<<NB, 256, SMEM_LSTM>>>(Whh);

    fc_out<<<BB, 256>>>(Wfc, bfc, out);
}